// round 11
// baseline (speedup 1.0000x reference)
#include <cuda_runtime.h>

// Problem constants
#define B_   32
#define T_   1024
#define H_   256
#define V_   5000
#define RBLK 32      // persistent blocks in the recurrence kernel

// ---------------------------------------------------------------------------
// Device scratch (static globals — no runtime allocation allowed)
// ---------------------------------------------------------------------------
__device__ float d_EW[(size_t)V_ * H_];            // EW[v][i] = emb[v]@Wx[i] + b1[i]   (5 MB)
__device__ float d_HS[(size_t)B_ * T_ * H_];       // HS[b][t][i] = hidden states        (32 MB)
__device__ float d_Hping[2][H_ * B_];              // ping-pong h, layout [i][b]
__device__ int   d_gbar;                           // grid barrier counter

// ---------------------------------------------------------------------------
// Generic fp32 GEMM:  C[m][n] = sum_k A[m][k] * B[n][k]  + bias[n]
// A: MxK row-major (stride lda), B: NxK row-major (stride ldb), C: MxN (ldc)
// 128x128 tile, BK=8, 256 threads, 8x8 per thread.
// ---------------------------------------------------------------------------
__global__ __launch_bounds__(256) void sgemm_nt_kernel(
    const float* __restrict__ A, int lda,
    const float* __restrict__ Bm, int ldb,
    const float* __restrict__ bias,
    float* __restrict__ C, int ldc,
    int M, int N, int K)
{
    __shared__ float As[8][128];
    __shared__ float Bs[8][128];

    const int tid = threadIdx.x;
    const int m0 = blockIdx.y * 128;
    const int n0 = blockIdx.x * 128;
    const int tx = tid & 15;          // 16 threads over N
    const int ty = tid >> 4;          // 16 threads over M
    const int lrow = tid >> 1;        // 0..127 : tile row for loading
    const int lk   = (tid & 1) * 4;   // 0 or 4 : k offset for loading

    float acc[8][8];
#pragma unroll
    for (int i = 0; i < 8; i++)
#pragma unroll
        for (int j = 0; j < 8; j++) acc[i][j] = 0.0f;

    for (int kt = 0; kt < K; kt += 8) {
        // Load A tile (guarded rows -> zeros)
        float4 a4 = make_float4(0.f, 0.f, 0.f, 0.f);
        int am = m0 + lrow;
        if (am < M) a4 = *(const float4*)&A[(size_t)am * lda + kt + lk];
        As[lk + 0][lrow] = a4.x;
        As[lk + 1][lrow] = a4.y;
        As[lk + 2][lrow] = a4.z;
        As[lk + 3][lrow] = a4.w;

        // Load B tile
        float4 b4 = make_float4(0.f, 0.f, 0.f, 0.f);
        int bn = n0 + lrow;
        if (bn < N) b4 = *(const float4*)&Bm[(size_t)bn * ldb + kt + lk];
        Bs[lk + 0][lrow] = b4.x;
        Bs[lk + 1][lrow] = b4.y;
        Bs[lk + 2][lrow] = b4.z;
        Bs[lk + 3][lrow] = b4.w;

        __syncthreads();

#pragma unroll
        for (int k = 0; k < 8; k++) {
            float a[8], bb[8];
            *(float4*)&a[0]  = *(const float4*)&As[k][ty * 8];
            *(float4*)&a[4]  = *(const float4*)&As[k][ty * 8 + 4];
            *(float4*)&bb[0] = *(const float4*)&Bs[k][tx * 8];
            *(float4*)&bb[4] = *(const float4*)&Bs[k][tx * 8 + 4];
#pragma unroll
            for (int i = 0; i < 8; i++)
#pragma unroll
                for (int j = 0; j < 8; j++)
                    acc[i][j] = fmaf(a[i], bb[j], acc[i][j]);
        }
        __syncthreads();
    }

    // Epilogue: add bias, guarded store
#pragma unroll
    for (int i = 0; i < 8; i++) {
        int m = m0 + ty * 8 + i;
        if (m >= M) continue;
#pragma unroll
        for (int j = 0; j < 8; j++) {
            int n = n0 + tx * 8 + j;
            if (n < N)
                C[(size_t)m * ldc + n] = acc[i][j] + bias[n];
        }
    }
}

// ---------------------------------------------------------------------------
// Fixup: reset grid barrier, zero h0, set EW row 0 to b1 (padding_idx=0).
// Runs every launch (graph-replay safe). Grid <<<32,256>>>.
// ---------------------------------------------------------------------------
__global__ void fixup_kernel(const float* __restrict__ b1)
{
    int g = blockIdx.x * 256 + threadIdx.x;
    if (g == 0) d_gbar = 0;
    if (g < H_ * B_) d_Hping[0][g] = 0.0f;
    if (g < H_) d_EW[g] = b1[g];
}

// ---------------------------------------------------------------------------
// Persistent RNN recurrence. 32 blocks x 256 threads.
// Block bk owns output channels i = bk*8 .. bk*8+7, for all 32 batches.
// Thread (warp iL, lane b) computes h_new[b][bk*8+iL].
// Per step: h_new = tanh(EW[token] + h @ Wh.T); grid barrier between steps.
// ---------------------------------------------------------------------------
__global__ __launch_bounds__(256) void rnn_kernel(
    const int* __restrict__ x,
    const float* __restrict__ W1,
    float* __restrict__ hT_out)
{
    __shared__ float whs[8][256];     // Wh rows for this block's 8 channels
    __shared__ float hsm[B_][260];    // h[b][j], padded stride 260 (conflict-free)

    const int tid = threadIdx.x;
    const int bk  = blockIdx.x;
    const int iL  = tid >> 5;         // warp id: local channel 0..7
    const int b   = tid & 31;         // lane: batch
    const int i   = bk * 8 + iL;      // global output channel

    // Load Wh rows once: whs[r][c] = W1[(bk*8+r)][256+c]
#pragma unroll
    for (int r = tid; r < 8 * 256; r += 256) {
        int rr = r >> 8, c = r & 255;
        whs[rr][c] = W1[(size_t)(bk * 8 + rr) * 512 + 256 + c];
    }

    const int* xb = x + b * T_;

    for (int t = 0; t < T_; ++t) {
        const int p = t & 1;
        const float* hin = d_Hping[p];

        // Load h (layout [j][b] in global) into hsm[b][j]; bypass L1 (cross-SM data)
        for (int r = tid; r < H_ * B_; r += 256)
            hsm[r & 31][r >> 5] = __ldcg(&hin[r]);
        __syncthreads();

        const int tok = xb[t];
        float acc = d_EW[(size_t)tok * H_ + i];
#pragma unroll
        for (int j = 0; j < H_; j += 4) {
            float4 h4 = *(const float4*)&hsm[b][j];
            float4 w4 = *(const float4*)&whs[iL][j];
            acc = fmaf(h4.x, w4.x, acc);
            acc = fmaf(h4.y, w4.y, acc);
            acc = fmaf(h4.z, w4.z, acc);
            acc = fmaf(h4.w, w4.w, acc);
        }
        float hv = tanhf(acc);

        __stcg(&d_Hping[p ^ 1][i * B_ + b], hv);                 // next-step input
        d_HS[((size_t)b * T_ + t) * H_ + i] = hv;                // for decode GEMM
        if (hT_out != nullptr && t == T_ - 1)
            hT_out[b * H_ + i] = hv;                             // final hidden state

        // Grid barrier (monotonic counter, reset each launch by fixup)
        __threadfence();
        __syncthreads();
        if (tid == 0) {
            atomicAdd(&d_gbar, 1);
            const int target = RBLK * (t + 1);
            while (atomicAdd(&d_gbar, 0) < target) { }
        }
        __syncthreads();
    }
}

// ---------------------------------------------------------------------------
// Launch
// Inputs: x[int32 B*T], emb[V*H], W1[H*2H], b1[H], Wd[V*H], bd[V]
// Output: out[B*T*V] fp32, then hT[B*H] fp32 (if out_size covers it)
// ---------------------------------------------------------------------------
extern "C" void kernel_launch(void* const* d_in, const int* in_sizes, int n_in,
                              void* d_out, int out_size)
{
    const int*   x   = (const int*)d_in[0];
    const float* emb = (const float*)d_in[1];
    const float* W1  = (const float*)d_in[2];
    const float* b1  = (const float*)d_in[3];
    const float* Wd  = (const float*)d_in[4];
    const float* bd  = (const float*)d_in[5];
    float* out = (float*)d_out;

    float *EW, *HS;
    cudaGetSymbolAddress((void**)&EW, d_EW);
    cudaGetSymbolAddress((void**)&HS, d_HS);

    // 1. EW = emb @ Wx.T + b1   (M=V, N=H, K=H; Wx = W1[:, :256], row stride 512)
    sgemm_nt_kernel<<<dim3(2, 40), 256>>>(emb, H_, W1, 512, b1, EW, H_, V_, H_, H_);

    // 2. Reset barrier, zero h0, EW[0] = b1 (padding_idx)
    fixup_kernel<<<32, 256>>>(b1);

    // 3. Sequential recurrence (persistent, grid-barrier per step)
    const size_t full = (size_t)B_ * T_ * V_ + (size_t)B_ * H_;
    float* hT = ((size_t)out_size >= full) ? out + (size_t)B_ * T_ * V_ : nullptr;
    rnn_kernel<<<RBLK, 256>>>(x, W1, hT);

    // 4. Decode: out = HS @ Wd.T + bd   (M=B*T, N=V, K=H)
    sgemm_nt_kernel<<<dim3(40, 256), 256>>>(HS, H_, Wd, H_, bd, out, V_,
                                            B_ * T_, V_, H_);
}

// round 12
// speedup vs baseline: 1.1959x; 1.1959x over previous
#include <cuda_runtime.h>
#include <cuda_bf16.h>
#include <cstdint>

// Problem constants
#define B_   32
#define T_   1024
#define H_   256
#define V_   5000
#define RBLK 32      // persistent blocks in the recurrence kernel

#define M_DEC (B_ * T_)     // 32768
#define KSPL  768           // split-K: [hi | lo | hi] x [hi | hi | lo]
#define SROW  40            // padded bf16 elems per smem k-row (80B -> conflict-free ldmatrix)

// ---------------------------------------------------------------------------
// Device scratch (static globals — no runtime allocation allowed)
// ---------------------------------------------------------------------------
__device__ float d_EW[(size_t)V_ * H_];                 // emb@Wx.T + b1
__device__ float d_HS[(size_t)B_ * T_ * H_];            // hidden states fp32
__device__ float d_Hping[2][H_ * B_];                   // ping-pong h, layout [i][b]
__device__ int   d_gbar;                                // grid barrier counter
__device__ __nv_bfloat16 d_A2[(size_t)M_DEC * KSPL];    // [m][768] = [hi|lo|hi](HS)
__device__ __nv_bfloat16 d_B2[(size_t)V_ * KSPL];       // [v][768] = [hi|hi|lo](Wd)

// ---------------------------------------------------------------------------
// Generic fp32 GEMM (used for EW precompute only):
// C[m][n] = sum_k A[m][k]*B[n][k] + bias[n]
// ---------------------------------------------------------------------------
__global__ __launch_bounds__(256) void sgemm_nt_kernel(
    const float* __restrict__ A, int lda,
    const float* __restrict__ Bm, int ldb,
    const float* __restrict__ bias,
    float* __restrict__ C, int ldc,
    int M, int N, int K)
{
    __shared__ float As[8][128];
    __shared__ float Bs[8][128];

    const int tid = threadIdx.x;
    const int m0 = blockIdx.y * 128;
    const int n0 = blockIdx.x * 128;
    const int tx = tid & 15;
    const int ty = tid >> 4;
    const int lrow = tid >> 1;
    const int lk   = (tid & 1) * 4;

    float acc[8][8];
#pragma unroll
    for (int i = 0; i < 8; i++)
#pragma unroll
        for (int j = 0; j < 8; j++) acc[i][j] = 0.0f;

    for (int kt = 0; kt < K; kt += 8) {
        float4 a4 = make_float4(0.f, 0.f, 0.f, 0.f);
        int am = m0 + lrow;
        if (am < M) a4 = *(const float4*)&A[(size_t)am * lda + kt + lk];
        As[lk + 0][lrow] = a4.x; As[lk + 1][lrow] = a4.y;
        As[lk + 2][lrow] = a4.z; As[lk + 3][lrow] = a4.w;

        float4 b4 = make_float4(0.f, 0.f, 0.f, 0.f);
        int bn = n0 + lrow;
        if (bn < N) b4 = *(const float4*)&Bm[(size_t)bn * ldb + kt + lk];
        Bs[lk + 0][lrow] = b4.x; Bs[lk + 1][lrow] = b4.y;
        Bs[lk + 2][lrow] = b4.z; Bs[lk + 3][lrow] = b4.w;

        __syncthreads();
#pragma unroll
        for (int k = 0; k < 8; k++) {
            float a[8], bb[8];
            *(float4*)&a[0]  = *(const float4*)&As[k][ty * 8];
            *(float4*)&a[4]  = *(const float4*)&As[k][ty * 8 + 4];
            *(float4*)&bb[0] = *(const float4*)&Bs[k][tx * 8];
            *(float4*)&bb[4] = *(const float4*)&Bs[k][tx * 8 + 4];
#pragma unroll
            for (int i = 0; i < 8; i++)
#pragma unroll
                for (int j = 0; j < 8; j++)
                    acc[i][j] = fmaf(a[i], bb[j], acc[i][j]);
        }
        __syncthreads();
    }

#pragma unroll
    for (int i = 0; i < 8; i++) {
        int m = m0 + ty * 8 + i;
        if (m >= M) continue;
#pragma unroll
        for (int j = 0; j < 8; j++) {
            int n = n0 + tx * 8 + j;
            if (n < N)
                C[(size_t)m * ldc + n] = acc[i][j] + bias[n];
        }
    }
}

// ---------------------------------------------------------------------------
// Fixup: reset grid barrier, zero h0, set EW row 0 to b1 (padding_idx=0).
// ---------------------------------------------------------------------------
__global__ void fixup_kernel(const float* __restrict__ b1)
{
    int g = blockIdx.x * 256 + threadIdx.x;
    if (g == 0) d_gbar = 0;
    if (g < H_ * B_) d_Hping[0][g] = 0.0f;
    if (g < H_) d_EW[g] = b1[g];
}

// ---------------------------------------------------------------------------
// Persistent RNN recurrence (unchanged from passing R11 kernel).
// ---------------------------------------------------------------------------
__global__ __launch_bounds__(256) void rnn_kernel(
    const int* __restrict__ x,
    const float* __restrict__ W1,
    float* __restrict__ hT_out)
{
    __shared__ float whs[8][256];
    __shared__ float hsm[B_][260];

    const int tid = threadIdx.x;
    const int bk  = blockIdx.x;
    const int iL  = tid >> 5;
    const int b   = tid & 31;
    const int i   = bk * 8 + iL;

#pragma unroll
    for (int r = tid; r < 8 * 256; r += 256) {
        int rr = r >> 8, c = r & 255;
        whs[rr][c] = W1[(size_t)(bk * 8 + rr) * 512 + 256 + c];
    }

    const int* xb = x + b * T_;

    for (int t = 0; t < T_; ++t) {
        const int p = t & 1;
        const float* hin = d_Hping[p];

        for (int r = tid; r < H_ * B_; r += 256)
            hsm[r & 31][r >> 5] = __ldcg(&hin[r]);
        __syncthreads();

        const int tok = xb[t];
        float acc = d_EW[(size_t)tok * H_ + i];
#pragma unroll
        for (int j = 0; j < H_; j += 4) {
            float4 h4 = *(const float4*)&hsm[b][j];
            float4 w4 = *(const float4*)&whs[iL][j];
            acc = fmaf(h4.x, w4.x, acc);
            acc = fmaf(h4.y, w4.y, acc);
            acc = fmaf(h4.z, w4.z, acc);
            acc = fmaf(h4.w, w4.w, acc);
        }
        float hv = tanhf(acc);

        __stcg(&d_Hping[p ^ 1][i * B_ + b], hv);
        d_HS[((size_t)b * T_ + t) * H_ + i] = hv;
        if (hT_out != nullptr && t == T_ - 1)
            hT_out[b * H_ + i] = hv;

        __threadfence();
        __syncthreads();
        if (tid == 0) {
            atomicAdd(&d_gbar, 1);
            const int target = RBLK * (t + 1);
            while (atomicAdd(&d_gbar, 0) < target) { }
        }
        __syncthreads();
    }
}

// ---------------------------------------------------------------------------
// bf16 hi/lo split conversion kernels
// ---------------------------------------------------------------------------
__device__ __forceinline__ void split2(float x, __nv_bfloat16& hi, __nv_bfloat16& lo)
{
    hi = __float2bfloat16(x);
    lo = __float2bfloat16(x - __bfloat162float(hi));
}

__global__ void convertA_kernel()   // d_HS -> d_A2  [hi | lo | hi]
{
    size_t g = (size_t)blockIdx.x * 256 + threadIdx.x;   // < M_DEC*H_
    float x = d_HS[g];
    __nv_bfloat16 hi, lo; split2(x, hi, lo);
    size_t m = g >> 8; int i = (int)(g & 255);
    __nv_bfloat16* row = d_A2 + m * KSPL;
    row[i] = hi; row[256 + i] = lo; row[512 + i] = hi;
}

__global__ void convertB_kernel(const float* __restrict__ Wd)  // -> d_B2 [hi | hi | lo]
{
    size_t g = (size_t)blockIdx.x * 256 + threadIdx.x;   // < V_*H_
    float x = Wd[g];
    __nv_bfloat16 hi, lo; split2(x, hi, lo);
    size_t n = g >> 8; int i = (int)(g & 255);
    __nv_bfloat16* row = d_B2 + n * KSPL;
    row[i] = hi; row[256 + i] = hi; row[512 + i] = lo;
}

// ---------------------------------------------------------------------------
// Tensor-core decode GEMM: C[M_DEC][V_] = A2 @ B2^T + bd   (bf16 in, fp32 acc)
// 128x128 block tile, BK=32, 8 warps (warp tile 32x64), mma.m16n8k16.bf16.
// ---------------------------------------------------------------------------
__device__ __forceinline__ uint32_t smem_u32(const void* p)
{
    return (uint32_t)__cvta_generic_to_shared(p);
}
__device__ __forceinline__ void ldsm4(uint32_t addr,
                                      uint32_t& r0, uint32_t& r1, uint32_t& r2, uint32_t& r3)
{
    asm volatile("ldmatrix.sync.aligned.m8n8.x4.shared.b16 {%0,%1,%2,%3}, [%4];"
                 : "=r"(r0), "=r"(r1), "=r"(r2), "=r"(r3) : "r"(addr));
}
__device__ __forceinline__ void mma16816(float* d, const uint32_t* a, uint32_t b0, uint32_t b1)
{
    asm volatile("mma.sync.aligned.m16n8k16.row.col.f32.bf16.bf16.f32 "
                 "{%0,%1,%2,%3}, {%4,%5,%6,%7}, {%8,%9}, {%0,%1,%2,%3};"
                 : "+f"(d[0]), "+f"(d[1]), "+f"(d[2]), "+f"(d[3])
                 : "r"(a[0]), "r"(a[1]), "r"(a[2]), "r"(a[3]), "r"(b0), "r"(b1));
}

__global__ __launch_bounds__(256) void decode_mma_kernel(
    const __nv_bfloat16* __restrict__ A2,
    const __nv_bfloat16* __restrict__ B2,
    const float* __restrict__ bias,
    float* __restrict__ C)
{
    __shared__ __nv_bfloat16 As[2][128 * SROW];   // 10KB per stage
    __shared__ __nv_bfloat16 Bs[2][128 * SROW];

    const int tid  = threadIdx.x;
    const int lane = tid & 31;
    const int w    = tid >> 5;
    const int m0   = blockIdx.y * 128;
    const int n0   = blockIdx.x * 128;
    const int wm   = (w >> 1) * 32;    // warp m offset (4 warps over M)
    const int wn   = (w & 1) * 64;     // warp n offset (2 warps over N)

    // tile loaders: thread -> (row, 32B half)
    const int lr = tid >> 1;           // 0..127
    const int lh = (tid & 1) * 16;     // elem offset 0 or 16

    const __nv_bfloat16* Ag = A2 + (size_t)(m0 + lr) * KSPL + lh;
    const bool bvalid = (n0 + lr) < V_;
    const __nv_bfloat16* Bg = B2 + (size_t)(bvalid ? (n0 + lr) : 0) * KSPL + lh;

    float acc[2][8][4];
#pragma unroll
    for (int mi = 0; mi < 2; mi++)
#pragma unroll
        for (int nj = 0; nj < 8; nj++)
#pragma unroll
            for (int q = 0; q < 4; q++) acc[mi][nj][q] = 0.0f;

    uint4 ra0, ra1, rb0, rb1;
    const uint4 z4 = make_uint4(0u, 0u, 0u, 0u);

    // prologue: load tile kt=0
    ra0 = *(const uint4*)(Ag + 0);
    ra1 = *(const uint4*)(Ag + 8);
    rb0 = bvalid ? *(const uint4*)(Bg + 0) : z4;
    rb1 = bvalid ? *(const uint4*)(Bg + 8) : z4;
    {
        const int so = lr * SROW + lh;
        *(uint4*)&As[0][so]     = ra0;  *(uint4*)&As[0][so + 8] = ra1;
        *(uint4*)&Bs[0][so]     = rb0;  *(uint4*)&Bs[0][so + 8] = rb1;
    }
    __syncthreads();

    // ldmatrix lane address components
    const int a_row = (lane & 15);            // within 16-row subtile
    const int a_kh  = (lane >> 4) * 8;        // k half
    const int b_row = ((lane >> 4) << 3) + (lane & 7);
    const int b_kh  = ((lane >> 3) & 1) * 8;

    int s = 0;
    for (int kt = 0; kt < KSPL; kt += 32) {
        const bool more = (kt + 32) < KSPL;
        if (more) {
            ra0 = *(const uint4*)(Ag + kt + 32);
            ra1 = *(const uint4*)(Ag + kt + 40);
            rb0 = bvalid ? *(const uint4*)(Bg + kt + 32) : z4;
            rb1 = bvalid ? *(const uint4*)(Bg + kt + 40) : z4;
        }

#pragma unroll
        for (int ks = 0; ks < 2; ks++) {
            uint32_t afr[2][4], bfr[4][4];
            const int acol = ks * 16 + a_kh;
            const int bcol = ks * 16 + b_kh;
#pragma unroll
            for (int mi = 0; mi < 2; mi++)
                ldsm4(smem_u32(&As[s][(wm + mi * 16 + a_row) * SROW + acol]),
                      afr[mi][0], afr[mi][1], afr[mi][2], afr[mi][3]);
#pragma unroll
            for (int nj = 0; nj < 4; nj++)
                ldsm4(smem_u32(&Bs[s][(wn + nj * 16 + b_row) * SROW + bcol]),
                      bfr[nj][0], bfr[nj][1], bfr[nj][2], bfr[nj][3]);
#pragma unroll
            for (int mi = 0; mi < 2; mi++)
#pragma unroll
                for (int n8 = 0; n8 < 8; n8++)
                    mma16816(acc[mi][n8], afr[mi],
                             bfr[n8 >> 1][(n8 & 1) * 2], bfr[n8 >> 1][(n8 & 1) * 2 + 1]);
        }

        if (more) {
            const int ns = s ^ 1;
            const int so = lr * SROW + lh;
            *(uint4*)&As[ns][so]     = ra0;  *(uint4*)&As[ns][so + 8] = ra1;
            *(uint4*)&Bs[ns][so]     = rb0;  *(uint4*)&Bs[ns][so + 8] = rb1;
            __syncthreads();
            s = ns;
        }
    }

    // epilogue: bias + guarded fp32 store
    const int g  = lane >> 2;
    const int t2 = (lane & 3) * 2;
#pragma unroll
    for (int mi = 0; mi < 2; mi++) {
#pragma unroll
        for (int n8 = 0; n8 < 8; n8++) {
            const int col = n0 + wn + n8 * 8 + t2;
            if (col >= V_) continue;
            const float bv0 = bias[col], bv1 = bias[col + 1];
            const int r0 = m0 + wm + mi * 16 + g;
            float2 v0 = make_float2(acc[mi][n8][0] + bv0, acc[mi][n8][1] + bv1);
            float2 v1 = make_float2(acc[mi][n8][2] + bv0, acc[mi][n8][3] + bv1);
            *(float2*)&C[(size_t)r0 * V_ + col]       = v0;
            *(float2*)&C[(size_t)(r0 + 8) * V_ + col] = v1;
        }
    }
}

// ---------------------------------------------------------------------------
// Launch
// Inputs: x[int32 B*T], emb[V*H], W1[H*2H], b1[H], Wd[V*H], bd[V]
// Output: out[B*T*V] fp32, then hT[B*H] fp32
// ---------------------------------------------------------------------------
extern "C" void kernel_launch(void* const* d_in, const int* in_sizes, int n_in,
                              void* d_out, int out_size)
{
    const int*   x   = (const int*)d_in[0];
    const float* emb = (const float*)d_in[1];
    const float* W1  = (const float*)d_in[2];
    const float* b1  = (const float*)d_in[3];
    const float* Wd  = (const float*)d_in[4];
    const float* bd  = (const float*)d_in[5];
    float* out = (float*)d_out;

    float *EW;
    __nv_bfloat16 *A2, *B2;
    cudaGetSymbolAddress((void**)&EW, d_EW);
    cudaGetSymbolAddress((void**)&A2, d_A2);
    cudaGetSymbolAddress((void**)&B2, d_B2);

    // 0. Wd -> bf16 hi/lo split (independent of recurrence)
    convertB_kernel<<<V_, 256>>>(Wd);

    // 1. EW = emb @ Wx.T + b1
    sgemm_nt_kernel<<<dim3(2, 40), 256>>>(emb, H_, W1, 512, b1, EW, H_, V_, H_, H_);

    // 2. Reset barrier, zero h0, EW[0] = b1 (padding_idx)
    fixup_kernel<<<32, 256>>>(b1);

    // 3. Sequential recurrence
    const size_t full = (size_t)B_ * T_ * V_ + (size_t)B_ * H_;
    float* hT = ((size_t)out_size >= full) ? out + (size_t)B_ * T_ * V_ : nullptr;
    rnn_kernel<<<RBLK, 256>>>(x, W1, hT);

    // 4. HS -> bf16 hi/lo split
    convertA_kernel<<<M_DEC, 256>>>();   // M_DEC*H_/256 = 32768 blocks

    // 5. Decode on tensor cores: out = A2 @ B2^T + bd
    decode_mma_kernel<<<dim3(40, 256), 256>>>(A2, B2, bd, out);
}

// round 13
// speedup vs baseline: 1.1978x; 1.0016x over previous
#include <cuda_runtime.h>
#include <cuda_bf16.h>
#include <cstdint>

// Problem constants
#define B_   32
#define T_   1024
#define H_   256
#define V_   5000
#define RBLK 32      // persistent blocks in the recurrence kernel

#define M_DEC (B_ * T_)     // 32768
#define KSPL  768           // split-K: [hi | lo | hi] x [hi | hi | lo]
#define SROW  40            // padded bf16 elems per smem k-row (80B -> conflict-free ldmatrix)

// ---------------------------------------------------------------------------
// Device scratch (static globals — no runtime allocation allowed)
// ---------------------------------------------------------------------------
__device__ float d_EW[(size_t)V_ * H_];                 // emb@Wx.T + b1
__device__ float d_HS[(size_t)B_ * T_ * H_];            // hidden states fp32
__device__ float d_Hping[2][H_ * B_];                   // ping-pong h, layout [i][b]
__device__ int   d_gbar;                                // grid barrier counter
__device__ __nv_bfloat16 d_A2[(size_t)M_DEC * KSPL];    // [m][768] = [hi|lo|hi](HS)
__device__ __nv_bfloat16 d_B2[(size_t)V_ * KSPL];       // [v][768] = [hi|hi|lo](Wd)

// ---------------------------------------------------------------------------
// Generic fp32 GEMM (used for EW precompute only):
// C[m][n] = sum_k A[m][k]*B[n][k] + bias[n]
// ---------------------------------------------------------------------------
__global__ __launch_bounds__(256) void sgemm_nt_kernel(
    const float* __restrict__ A, int lda,
    const float* __restrict__ Bm, int ldb,
    const float* __restrict__ bias,
    float* __restrict__ C, int ldc,
    int M, int N, int K)
{
    __shared__ float As[8][128];
    __shared__ float Bs[8][128];

    const int tid = threadIdx.x;
    const int m0 = blockIdx.y * 128;
    const int n0 = blockIdx.x * 128;
    const int tx = tid & 15;
    const int ty = tid >> 4;
    const int lrow = tid >> 1;
    const int lk   = (tid & 1) * 4;

    float acc[8][8];
#pragma unroll
    for (int i = 0; i < 8; i++)
#pragma unroll
        for (int j = 0; j < 8; j++) acc[i][j] = 0.0f;

    for (int kt = 0; kt < K; kt += 8) {
        float4 a4 = make_float4(0.f, 0.f, 0.f, 0.f);
        int am = m0 + lrow;
        if (am < M) a4 = *(const float4*)&A[(size_t)am * lda + kt + lk];
        As[lk + 0][lrow] = a4.x; As[lk + 1][lrow] = a4.y;
        As[lk + 2][lrow] = a4.z; As[lk + 3][lrow] = a4.w;

        float4 b4 = make_float4(0.f, 0.f, 0.f, 0.f);
        int bn = n0 + lrow;
        if (bn < N) b4 = *(const float4*)&Bm[(size_t)bn * ldb + kt + lk];
        Bs[lk + 0][lrow] = b4.x; Bs[lk + 1][lrow] = b4.y;
        Bs[lk + 2][lrow] = b4.z; Bs[lk + 3][lrow] = b4.w;

        __syncthreads();
#pragma unroll
        for (int k = 0; k < 8; k++) {
            float a[8], bb[8];
            *(float4*)&a[0]  = *(const float4*)&As[k][ty * 8];
            *(float4*)&a[4]  = *(const float4*)&As[k][ty * 8 + 4];
            *(float4*)&bb[0] = *(const float4*)&Bs[k][tx * 8];
            *(float4*)&bb[4] = *(const float4*)&Bs[k][tx * 8 + 4];
#pragma unroll
            for (int i = 0; i < 8; i++)
#pragma unroll
                for (int j = 0; j < 8; j++)
                    acc[i][j] = fmaf(a[i], bb[j], acc[i][j]);
        }
        __syncthreads();
    }

#pragma unroll
    for (int i = 0; i < 8; i++) {
        int m = m0 + ty * 8 + i;
        if (m >= M) continue;
#pragma unroll
        for (int j = 0; j < 8; j++) {
            int n = n0 + tx * 8 + j;
            if (n < N)
                C[(size_t)m * ldc + n] = acc[i][j] + bias[n];
        }
    }
}

// ---------------------------------------------------------------------------
// Fixup: reset grid barrier, zero h0, set EW row 0 to b1 (padding_idx=0).
// ---------------------------------------------------------------------------
__global__ void fixup_kernel(const float* __restrict__ b1)
{
    int g = blockIdx.x * 256 + threadIdx.x;
    if (g == 0) d_gbar = 0;
    if (g < H_ * B_) d_Hping[0][g] = 0.0f;
    if (g < H_) d_EW[g] = b1[g];
}

// ---------------------------------------------------------------------------
// Persistent RNN recurrence (unchanged from passing R11 kernel).
// ---------------------------------------------------------------------------
__global__ __launch_bounds__(256) void rnn_kernel(
    const int* __restrict__ x,
    const float* __restrict__ W1,
    float* __restrict__ hT_out)
{
    __shared__ float whs[8][256];
    __shared__ float hsm[B_][260];

    const int tid = threadIdx.x;
    const int bk  = blockIdx.x;
    const int iL  = tid >> 5;
    const int b   = tid & 31;
    const int i   = bk * 8 + iL;

#pragma unroll
    for (int r = tid; r < 8 * 256; r += 256) {
        int rr = r >> 8, c = r & 255;
        whs[rr][c] = W1[(size_t)(bk * 8 + rr) * 512 + 256 + c];
    }

    const int* xb = x + b * T_;

    for (int t = 0; t < T_; ++t) {
        const int p = t & 1;
        const float* hin = d_Hping[p];

        for (int r = tid; r < H_ * B_; r += 256)
            hsm[r & 31][r >> 5] = __ldcg(&hin[r]);
        __syncthreads();

        const int tok = xb[t];
        float acc = d_EW[(size_t)tok * H_ + i];
#pragma unroll
        for (int j = 0; j < H_; j += 4) {
            float4 h4 = *(const float4*)&hsm[b][j];
            float4 w4 = *(const float4*)&whs[iL][j];
            acc = fmaf(h4.x, w4.x, acc);
            acc = fmaf(h4.y, w4.y, acc);
            acc = fmaf(h4.z, w4.z, acc);
            acc = fmaf(h4.w, w4.w, acc);
        }
        float hv = tanhf(acc);

        __stcg(&d_Hping[p ^ 1][i * B_ + b], hv);
        d_HS[((size_t)b * T_ + t) * H_ + i] = hv;
        if (hT_out != nullptr && t == T_ - 1)
            hT_out[b * H_ + i] = hv;

        __threadfence();
        __syncthreads();
        if (tid == 0) {
            atomicAdd(&d_gbar, 1);
            const int target = RBLK * (t + 1);
            while (atomicAdd(&d_gbar, 0) < target) { }
        }
        __syncthreads();
    }
}

// ---------------------------------------------------------------------------
// bf16 hi/lo split conversion kernels
// ---------------------------------------------------------------------------
__device__ __forceinline__ void split2(float x, __nv_bfloat16& hi, __nv_bfloat16& lo)
{
    hi = __float2bfloat16(x);
    lo = __float2bfloat16(x - __bfloat162float(hi));
}

__global__ void convertA_kernel()   // d_HS -> d_A2  [hi | lo | hi]
{
    size_t g = (size_t)blockIdx.x * 256 + threadIdx.x;   // < M_DEC*H_
    float x = d_HS[g];
    __nv_bfloat16 hi, lo; split2(x, hi, lo);
    size_t m = g >> 8; int i = (int)(g & 255);
    __nv_bfloat16* row = d_A2 + m * KSPL;
    row[i] = hi; row[256 + i] = lo; row[512 + i] = hi;
}

__global__ void convertB_kernel(const float* __restrict__ Wd)  // -> d_B2 [hi | hi | lo]
{
    size_t g = (size_t)blockIdx.x * 256 + threadIdx.x;   // < V_*H_
    float x = Wd[g];
    __nv_bfloat16 hi, lo; split2(x, hi, lo);
    size_t n = g >> 8; int i = (int)(g & 255);
    __nv_bfloat16* row = d_B2 + n * KSPL;
    row[i] = hi; row[256 + i] = hi; row[512 + i] = lo;
}

// ---------------------------------------------------------------------------
// Tensor-core decode GEMM: C[M_DEC][V_] = A2 @ B2^T + bd   (bf16 in, fp32 acc)
// 128x128 block tile, BK=32, 8 warps (warp tile 32x64), mma.m16n8k16.bf16.
// ---------------------------------------------------------------------------
__device__ __forceinline__ uint32_t smem_u32(const void* p)
{
    return (uint32_t)__cvta_generic_to_shared(p);
}
__device__ __forceinline__ void ldsm4(uint32_t addr,
                                      uint32_t& r0, uint32_t& r1, uint32_t& r2, uint32_t& r3)
{
    asm volatile("ldmatrix.sync.aligned.m8n8.x4.shared.b16 {%0,%1,%2,%3}, [%4];"
                 : "=r"(r0), "=r"(r1), "=r"(r2), "=r"(r3) : "r"(addr));
}
__device__ __forceinline__ void mma16816(float* d, const uint32_t* a, uint32_t b0, uint32_t b1)
{
    asm volatile("mma.sync.aligned.m16n8k16.row.col.f32.bf16.bf16.f32 "
                 "{%0,%1,%2,%3}, {%4,%5,%6,%7}, {%8,%9}, {%0,%1,%2,%3};"
                 : "+f"(d[0]), "+f"(d[1]), "+f"(d[2]), "+f"(d[3])
                 : "r"(a[0]), "r"(a[1]), "r"(a[2]), "r"(a[3]), "r"(b0), "r"(b1));
}

__global__ __launch_bounds__(256) void decode_mma_kernel(
    const __nv_bfloat16* __restrict__ A2,
    const __nv_bfloat16* __restrict__ B2,
    const float* __restrict__ bias,
    float* __restrict__ C)
{
    __shared__ __nv_bfloat16 As[2][128 * SROW];   // 10KB per stage
    __shared__ __nv_bfloat16 Bs[2][128 * SROW];

    const int tid  = threadIdx.x;
    const int lane = tid & 31;
    const int w    = tid >> 5;
    const int m0   = blockIdx.y * 128;
    const int n0   = blockIdx.x * 128;
    const int wm   = (w >> 1) * 32;    // warp m offset (4 warps over M)
    const int wn   = (w & 1) * 64;     // warp n offset (2 warps over N)

    // tile loaders: thread -> (row, 32B half)
    const int lr = tid >> 1;           // 0..127
    const int lh = (tid & 1) * 16;     // elem offset 0 or 16

    const __nv_bfloat16* Ag = A2 + (size_t)(m0 + lr) * KSPL + lh;
    const bool bvalid = (n0 + lr) < V_;
    const __nv_bfloat16* Bg = B2 + (size_t)(bvalid ? (n0 + lr) : 0) * KSPL + lh;

    float acc[2][8][4];
#pragma unroll
    for (int mi = 0; mi < 2; mi++)
#pragma unroll
        for (int nj = 0; nj < 8; nj++)
#pragma unroll
            for (int q = 0; q < 4; q++) acc[mi][nj][q] = 0.0f;

    uint4 ra0, ra1, rb0, rb1;
    const uint4 z4 = make_uint4(0u, 0u, 0u, 0u);

    // prologue: load tile kt=0
    ra0 = *(const uint4*)(Ag + 0);
    ra1 = *(const uint4*)(Ag + 8);
    rb0 = bvalid ? *(const uint4*)(Bg + 0) : z4;
    rb1 = bvalid ? *(const uint4*)(Bg + 8) : z4;
    {
        const int so = lr * SROW + lh;
        *(uint4*)&As[0][so]     = ra0;  *(uint4*)&As[0][so + 8] = ra1;
        *(uint4*)&Bs[0][so]     = rb0;  *(uint4*)&Bs[0][so + 8] = rb1;
    }
    __syncthreads();

    // ldmatrix lane address components
    const int a_row = (lane & 15);            // within 16-row subtile
    const int a_kh  = (lane >> 4) * 8;        // k half
    const int b_row = ((lane >> 4) << 3) + (lane & 7);
    const int b_kh  = ((lane >> 3) & 1) * 8;

    int s = 0;
    for (int kt = 0; kt < KSPL; kt += 32) {
        const bool more = (kt + 32) < KSPL;
        if (more) {
            ra0 = *(const uint4*)(Ag + kt + 32);
            ra1 = *(const uint4*)(Ag + kt + 40);
            rb0 = bvalid ? *(const uint4*)(Bg + kt + 32) : z4;
            rb1 = bvalid ? *(const uint4*)(Bg + kt + 40) : z4;
        }

#pragma unroll
        for (int ks = 0; ks < 2; ks++) {
            uint32_t afr[2][4], bfr[4][4];
            const int acol = ks * 16 + a_kh;
            const int bcol = ks * 16 + b_kh;
#pragma unroll
            for (int mi = 0; mi < 2; mi++)
                ldsm4(smem_u32(&As[s][(wm + mi * 16 + a_row) * SROW + acol]),
                      afr[mi][0], afr[mi][1], afr[mi][2], afr[mi][3]);
#pragma unroll
            for (int nj = 0; nj < 4; nj++)
                ldsm4(smem_u32(&Bs[s][(wn + nj * 16 + b_row) * SROW + bcol]),
                      bfr[nj][0], bfr[nj][1], bfr[nj][2], bfr[nj][3]);
#pragma unroll
            for (int mi = 0; mi < 2; mi++)
#pragma unroll
                for (int n8 = 0; n8 < 8; n8++)
                    mma16816(acc[mi][n8], afr[mi],
                             bfr[n8 >> 1][(n8 & 1) * 2], bfr[n8 >> 1][(n8 & 1) * 2 + 1]);
        }

        if (more) {
            const int ns = s ^ 1;
            const int so = lr * SROW + lh;
            *(uint4*)&As[ns][so]     = ra0;  *(uint4*)&As[ns][so + 8] = ra1;
            *(uint4*)&Bs[ns][so]     = rb0;  *(uint4*)&Bs[ns][so + 8] = rb1;
            __syncthreads();
            s = ns;
        }
    }

    // epilogue: bias + guarded fp32 store
    const int g  = lane >> 2;
    const int t2 = (lane & 3) * 2;
#pragma unroll
    for (int mi = 0; mi < 2; mi++) {
#pragma unroll
        for (int n8 = 0; n8 < 8; n8++) {
            const int col = n0 + wn + n8 * 8 + t2;
            if (col >= V_) continue;
            const float bv0 = bias[col], bv1 = bias[col + 1];
            const int r0 = m0 + wm + mi * 16 + g;
            float2 v0 = make_float2(acc[mi][n8][0] + bv0, acc[mi][n8][1] + bv1);
            float2 v1 = make_float2(acc[mi][n8][2] + bv0, acc[mi][n8][3] + bv1);
            *(float2*)&C[(size_t)r0 * V_ + col]       = v0;
            *(float2*)&C[(size_t)(r0 + 8) * V_ + col] = v1;
        }
    }
}

// ---------------------------------------------------------------------------
// Launch
// Inputs: x[int32 B*T], emb[V*H], W1[H*2H], b1[H], Wd[V*H], bd[V]
// Output: out[B*T*V] fp32, then hT[B*H] fp32
// ---------------------------------------------------------------------------
extern "C" void kernel_launch(void* const* d_in, const int* in_sizes, int n_in,
                              void* d_out, int out_size)
{
    const int*   x   = (const int*)d_in[0];
    const float* emb = (const float*)d_in[1];
    const float* W1  = (const float*)d_in[2];
    const float* b1  = (const float*)d_in[3];
    const float* Wd  = (const float*)d_in[4];
    const float* bd  = (const float*)d_in[5];
    float* out = (float*)d_out;

    float *EW;
    __nv_bfloat16 *A2, *B2;
    cudaGetSymbolAddress((void**)&EW, d_EW);
    cudaGetSymbolAddress((void**)&A2, d_A2);
    cudaGetSymbolAddress((void**)&B2, d_B2);

    // 0. Wd -> bf16 hi/lo split (independent of recurrence)
    convertB_kernel<<<V_, 256>>>(Wd);

    // 1. EW = emb @ Wx.T + b1
    sgemm_nt_kernel<<<dim3(2, 40), 256>>>(emb, H_, W1, 512, b1, EW, H_, V_, H_, H_);

    // 2. Reset barrier, zero h0, EW[0] = b1 (padding_idx)
    fixup_kernel<<<32, 256>>>(b1);

    // 3. Sequential recurrence
    const size_t full = (size_t)B_ * T_ * V_ + (size_t)B_ * H_;
    float* hT = ((size_t)out_size >= full) ? out + (size_t)B_ * T_ * V_ : nullptr;
    rnn_kernel<<<RBLK, 256>>>(x, W1, hT);

    // 4. HS -> bf16 hi/lo split
    convertA_kernel<<<M_DEC, 256>>>();   // M_DEC*H_/256 = 32768 blocks

    // 5. Decode on tensor cores: out = A2 @ B2^T + bd
    decode_mma_kernel<<<dim3(40, 256), 256>>>(A2, B2, bd, out);
}

// round 14
// speedup vs baseline: 1.2091x; 1.0095x over previous
#include <cuda_runtime.h>
#include <cuda_bf16.h>
#include <cstdint>

// Problem constants
#define B_   32
#define T_   1024
#define H_   256
#define V_   5000
#define RBLK 32      // persistent blocks in the recurrence kernel

#define M_DEC (B_ * T_)     // 32768
#define KSPL  768           // split-K: [hi | lo | hi] x [hi | hi | lo]
#define SROW  40            // padded bf16 elems per smem k-row (80B -> conflict-free ldmatrix)

// ---------------------------------------------------------------------------
// Device scratch (static globals — no runtime allocation allowed)
// ---------------------------------------------------------------------------
__device__ float d_EW[(size_t)V_ * H_];                 // emb@Wx.T + b1
__device__ float d_HS[(size_t)B_ * T_ * H_];            // hidden states fp32
__device__ float d_Hping[2][H_ * B_];                   // ping-pong h, layout [i][b]
__device__ int   d_gbar;                                // grid barrier counter
__device__ __nv_bfloat16 d_A2[(size_t)M_DEC * KSPL];    // [m][768] = [hi|lo|hi](HS)
__device__ __nv_bfloat16 d_B2[(size_t)V_ * KSPL];       // [v][768] = [hi|hi|lo](Wd)

// ---------------------------------------------------------------------------
// Generic fp32 GEMM (used for EW precompute only):
// C[m][n] = sum_k A[m][k]*B[n][k] + bias[n]
// ---------------------------------------------------------------------------
__global__ __launch_bounds__(256) void sgemm_nt_kernel(
    const float* __restrict__ A, int lda,
    const float* __restrict__ Bm, int ldb,
    const float* __restrict__ bias,
    float* __restrict__ C, int ldc,
    int M, int N, int K)
{
    __shared__ float As[8][128];
    __shared__ float Bs[8][128];

    const int tid = threadIdx.x;
    const int m0 = blockIdx.y * 128;
    const int n0 = blockIdx.x * 128;
    const int tx = tid & 15;
    const int ty = tid >> 4;
    const int lrow = tid >> 1;
    const int lk   = (tid & 1) * 4;

    float acc[8][8];
#pragma unroll
    for (int i = 0; i < 8; i++)
#pragma unroll
        for (int j = 0; j < 8; j++) acc[i][j] = 0.0f;

    for (int kt = 0; kt < K; kt += 8) {
        float4 a4 = make_float4(0.f, 0.f, 0.f, 0.f);
        int am = m0 + lrow;
        if (am < M) a4 = *(const float4*)&A[(size_t)am * lda + kt + lk];
        As[lk + 0][lrow] = a4.x; As[lk + 1][lrow] = a4.y;
        As[lk + 2][lrow] = a4.z; As[lk + 3][lrow] = a4.w;

        float4 b4 = make_float4(0.f, 0.f, 0.f, 0.f);
        int bn = n0 + lrow;
        if (bn < N) b4 = *(const float4*)&Bm[(size_t)bn * ldb + kt + lk];
        Bs[lk + 0][lrow] = b4.x; Bs[lk + 1][lrow] = b4.y;
        Bs[lk + 2][lrow] = b4.z; Bs[lk + 3][lrow] = b4.w;

        __syncthreads();
#pragma unroll
        for (int k = 0; k < 8; k++) {
            float a[8], bb[8];
            *(float4*)&a[0]  = *(const float4*)&As[k][ty * 8];
            *(float4*)&a[4]  = *(const float4*)&As[k][ty * 8 + 4];
            *(float4*)&bb[0] = *(const float4*)&Bs[k][tx * 8];
            *(float4*)&bb[4] = *(const float4*)&Bs[k][tx * 8 + 4];
#pragma unroll
            for (int i = 0; i < 8; i++)
#pragma unroll
                for (int j = 0; j < 8; j++)
                    acc[i][j] = fmaf(a[i], bb[j], acc[i][j]);
        }
        __syncthreads();
    }

#pragma unroll
    for (int i = 0; i < 8; i++) {
        int m = m0 + ty * 8 + i;
        if (m >= M) continue;
#pragma unroll
        for (int j = 0; j < 8; j++) {
            int n = n0 + tx * 8 + j;
            if (n < N)
                C[(size_t)m * ldc + n] = acc[i][j] + bias[n];
        }
    }
}

// ---------------------------------------------------------------------------
// Fixup: reset grid barrier, zero h0, set EW row 0 to b1 (padding_idx=0).
// ---------------------------------------------------------------------------
__global__ void fixup_kernel(const float* __restrict__ b1)
{
    int g = blockIdx.x * 256 + threadIdx.x;
    if (g == 0) d_gbar = 0;
    if (g < H_ * B_) d_Hping[0][g] = 0.0f;
    if (g < H_) d_EW[g] = b1[g];
}

// ---------------------------------------------------------------------------
// Persistent RNN recurrence (unchanged from passing R11 kernel).
// ---------------------------------------------------------------------------
__global__ __launch_bounds__(256) void rnn_kernel(
    const int* __restrict__ x,
    const float* __restrict__ W1,
    float* __restrict__ hT_out)
{
    __shared__ float whs[8][256];
    __shared__ float hsm[B_][260];

    const int tid = threadIdx.x;
    const int bk  = blockIdx.x;
    const int iL  = tid >> 5;
    const int b   = tid & 31;
    const int i   = bk * 8 + iL;

#pragma unroll
    for (int r = tid; r < 8 * 256; r += 256) {
        int rr = r >> 8, c = r & 255;
        whs[rr][c] = W1[(size_t)(bk * 8 + rr) * 512 + 256 + c];
    }

    const int* xb = x + b * T_;

    for (int t = 0; t < T_; ++t) {
        const int p = t & 1;
        const float* hin = d_Hping[p];

        for (int r = tid; r < H_ * B_; r += 256)
            hsm[r & 31][r >> 5] = __ldcg(&hin[r]);
        __syncthreads();

        const int tok = xb[t];
        float acc = d_EW[(size_t)tok * H_ + i];
#pragma unroll
        for (int j = 0; j < H_; j += 4) {
            float4 h4 = *(const float4*)&hsm[b][j];
            float4 w4 = *(const float4*)&whs[iL][j];
            acc = fmaf(h4.x, w4.x, acc);
            acc = fmaf(h4.y, w4.y, acc);
            acc = fmaf(h4.z, w4.z, acc);
            acc = fmaf(h4.w, w4.w, acc);
        }
        float hv = tanhf(acc);

        __stcg(&d_Hping[p ^ 1][i * B_ + b], hv);
        d_HS[((size_t)b * T_ + t) * H_ + i] = hv;
        if (hT_out != nullptr && t == T_ - 1)
            hT_out[b * H_ + i] = hv;

        __threadfence();
        __syncthreads();
        if (tid == 0) {
            atomicAdd(&d_gbar, 1);
            const int target = RBLK * (t + 1);
            while (atomicAdd(&d_gbar, 0) < target) { }
        }
        __syncthreads();
    }
}

// ---------------------------------------------------------------------------
// bf16 hi/lo split conversion kernels
// ---------------------------------------------------------------------------
__device__ __forceinline__ void split2(float x, __nv_bfloat16& hi, __nv_bfloat16& lo)
{
    hi = __float2bfloat16(x);
    lo = __float2bfloat16(x - __bfloat162float(hi));
}

__global__ void convertA_kernel()   // d_HS -> d_A2  [hi | lo | hi]
{
    size_t g = (size_t)blockIdx.x * 256 + threadIdx.x;   // < M_DEC*H_
    float x = d_HS[g];
    __nv_bfloat16 hi, lo; split2(x, hi, lo);
    size_t m = g >> 8; int i = (int)(g & 255);
    __nv_bfloat16* row = d_A2 + m * KSPL;
    row[i] = hi; row[256 + i] = lo; row[512 + i] = hi;
}

__global__ void convertB_kernel(const float* __restrict__ Wd)  // -> d_B2 [hi | hi | lo]
{
    size_t g = (size_t)blockIdx.x * 256 + threadIdx.x;   // < V_*H_
    float x = Wd[g];
    __nv_bfloat16 hi, lo; split2(x, hi, lo);
    size_t n = g >> 8; int i = (int)(g & 255);
    __nv_bfloat16* row = d_B2 + n * KSPL;
    row[i] = hi; row[256 + i] = hi; row[512 + i] = lo;
}

// ---------------------------------------------------------------------------
// Tensor-core decode GEMM: C[M_DEC][V_] = A2 @ B2^T + bd   (bf16 in, fp32 acc)
// 128x128 block tile, BK=32, 8 warps (warp tile 32x64), mma.m16n8k16.bf16.
// ---------------------------------------------------------------------------
__device__ __forceinline__ uint32_t smem_u32(const void* p)
{
    return (uint32_t)__cvta_generic_to_shared(p);
}
__device__ __forceinline__ void ldsm4(uint32_t addr,
                                      uint32_t& r0, uint32_t& r1, uint32_t& r2, uint32_t& r3)
{
    asm volatile("ldmatrix.sync.aligned.m8n8.x4.shared.b16 {%0,%1,%2,%3}, [%4];"
                 : "=r"(r0), "=r"(r1), "=r"(r2), "=r"(r3) : "r"(addr));
}
__device__ __forceinline__ void mma16816(float* d, const uint32_t* a, uint32_t b0, uint32_t b1)
{
    asm volatile("mma.sync.aligned.m16n8k16.row.col.f32.bf16.bf16.f32 "
                 "{%0,%1,%2,%3}, {%4,%5,%6,%7}, {%8,%9}, {%0,%1,%2,%3};"
                 : "+f"(d[0]), "+f"(d[1]), "+f"(d[2]), "+f"(d[3])
                 : "r"(a[0]), "r"(a[1]), "r"(a[2]), "r"(a[3]), "r"(b0), "r"(b1));
}

__global__ __launch_bounds__(256) void decode_mma_kernel(
    const __nv_bfloat16* __restrict__ A2,
    const __nv_bfloat16* __restrict__ B2,
    const float* __restrict__ bias,
    float* __restrict__ C)
{
    __shared__ __nv_bfloat16 As[2][128 * SROW];   // 10KB per stage
    __shared__ __nv_bfloat16 Bs[2][128 * SROW];

    const int tid  = threadIdx.x;
    const int lane = tid & 31;
    const int w    = tid >> 5;
    const int m0   = blockIdx.y * 128;
    const int n0   = blockIdx.x * 128;
    const int wm   = (w >> 1) * 32;    // warp m offset (4 warps over M)
    const int wn   = (w & 1) * 64;     // warp n offset (2 warps over N)

    // tile loaders: thread -> (row, 32B half)
    const int lr = tid >> 1;           // 0..127
    const int lh = (tid & 1) * 16;     // elem offset 0 or 16

    const __nv_bfloat16* Ag = A2 + (size_t)(m0 + lr) * KSPL + lh;
    const bool bvalid = (n0 + lr) < V_;
    const __nv_bfloat16* Bg = B2 + (size_t)(bvalid ? (n0 + lr) : 0) * KSPL + lh;

    float acc[2][8][4];
#pragma unroll
    for (int mi = 0; mi < 2; mi++)
#pragma unroll
        for (int nj = 0; nj < 8; nj++)
#pragma unroll
            for (int q = 0; q < 4; q++) acc[mi][nj][q] = 0.0f;

    uint4 ra0, ra1, rb0, rb1;
    const uint4 z4 = make_uint4(0u, 0u, 0u, 0u);

    // prologue: load tile kt=0
    ra0 = *(const uint4*)(Ag + 0);
    ra1 = *(const uint4*)(Ag + 8);
    rb0 = bvalid ? *(const uint4*)(Bg + 0) : z4;
    rb1 = bvalid ? *(const uint4*)(Bg + 8) : z4;
    {
        const int so = lr * SROW + lh;
        *(uint4*)&As[0][so]     = ra0;  *(uint4*)&As[0][so + 8] = ra1;
        *(uint4*)&Bs[0][so]     = rb0;  *(uint4*)&Bs[0][so + 8] = rb1;
    }
    __syncthreads();

    // ldmatrix lane address components
    const int a_row = (lane & 15);            // within 16-row subtile
    const int a_kh  = (lane >> 4) * 8;        // k half
    const int b_row = ((lane >> 4) << 3) + (lane & 7);
    const int b_kh  = ((lane >> 3) & 1) * 8;

    int s = 0;
    for (int kt = 0; kt < KSPL; kt += 32) {
        const bool more = (kt + 32) < KSPL;
        if (more) {
            ra0 = *(const uint4*)(Ag + kt + 32);
            ra1 = *(const uint4*)(Ag + kt + 40);
            rb0 = bvalid ? *(const uint4*)(Bg + kt + 32) : z4;
            rb1 = bvalid ? *(const uint4*)(Bg + kt + 40) : z4;
        }

#pragma unroll
        for (int ks = 0; ks < 2; ks++) {
            uint32_t afr[2][4], bfr[4][4];
            const int acol = ks * 16 + a_kh;
            const int bcol = ks * 16 + b_kh;
#pragma unroll
            for (int mi = 0; mi < 2; mi++)
                ldsm4(smem_u32(&As[s][(wm + mi * 16 + a_row) * SROW + acol]),
                      afr[mi][0], afr[mi][1], afr[mi][2], afr[mi][3]);
#pragma unroll
            for (int nj = 0; nj < 4; nj++)
                ldsm4(smem_u32(&Bs[s][(wn + nj * 16 + b_row) * SROW + bcol]),
                      bfr[nj][0], bfr[nj][1], bfr[nj][2], bfr[nj][3]);
#pragma unroll
            for (int mi = 0; mi < 2; mi++)
#pragma unroll
                for (int n8 = 0; n8 < 8; n8++)
                    mma16816(acc[mi][n8], afr[mi],
                             bfr[n8 >> 1][(n8 & 1) * 2], bfr[n8 >> 1][(n8 & 1) * 2 + 1]);
        }

        if (more) {
            const int ns = s ^ 1;
            const int so = lr * SROW + lh;
            *(uint4*)&As[ns][so]     = ra0;  *(uint4*)&As[ns][so + 8] = ra1;
            *(uint4*)&Bs[ns][so]     = rb0;  *(uint4*)&Bs[ns][so + 8] = rb1;
            __syncthreads();
            s = ns;
        }
    }

    // epilogue: bias + guarded fp32 store
    const int g  = lane >> 2;
    const int t2 = (lane & 3) * 2;
#pragma unroll
    for (int mi = 0; mi < 2; mi++) {
#pragma unroll
        for (int n8 = 0; n8 < 8; n8++) {
            const int col = n0 + wn + n8 * 8 + t2;
            if (col >= V_) continue;
            const float bv0 = bias[col], bv1 = bias[col + 1];
            const int r0 = m0 + wm + mi * 16 + g;
            float2 v0 = make_float2(acc[mi][n8][0] + bv0, acc[mi][n8][1] + bv1);
            float2 v1 = make_float2(acc[mi][n8][2] + bv0, acc[mi][n8][3] + bv1);
            *(float2*)&C[(size_t)r0 * V_ + col]       = v0;
            *(float2*)&C[(size_t)(r0 + 8) * V_ + col] = v1;
        }
    }
}

// ---------------------------------------------------------------------------
// Launch
// Inputs: x[int32 B*T], emb[V*H], W1[H*2H], b1[H], Wd[V*H], bd[V]
// Output: out[B*T*V] fp32, then hT[B*H] fp32
// ---------------------------------------------------------------------------
extern "C" void kernel_launch(void* const* d_in, const int* in_sizes, int n_in,
                              void* d_out, int out_size)
{
    const int*   x   = (const int*)d_in[0];
    const float* emb = (const float*)d_in[1];
    const float* W1  = (const float*)d_in[2];
    const float* b1  = (const float*)d_in[3];
    const float* Wd  = (const float*)d_in[4];
    const float* bd  = (const float*)d_in[5];
    float* out = (float*)d_out;

    float *EW;
    __nv_bfloat16 *A2, *B2;
    cudaGetSymbolAddress((void**)&EW, d_EW);
    cudaGetSymbolAddress((void**)&A2, d_A2);
    cudaGetSymbolAddress((void**)&B2, d_B2);

    // 0. Wd -> bf16 hi/lo split (independent of recurrence)
    convertB_kernel<<<V_, 256>>>(Wd);

    // 1. EW = emb @ Wx.T + b1
    sgemm_nt_kernel<<<dim3(2, 40), 256>>>(emb, H_, W1, 512, b1, EW, H_, V_, H_, H_);

    // 2. Reset barrier, zero h0, EW[0] = b1 (padding_idx)
    fixup_kernel<<<32, 256>>>(b1);

    // 3. Sequential recurrence
    const size_t full = (size_t)B_ * T_ * V_ + (size_t)B_ * H_;
    float* hT = ((size_t)out_size >= full) ? out + (size_t)B_ * T_ * V_ : nullptr;
    rnn_kernel<<<RBLK, 256>>>(x, W1, hT);

    // 4. HS -> bf16 hi/lo split
    convertA_kernel<<<M_DEC, 256>>>();   // M_DEC*H_/256 = 32768 blocks

    // 5. Decode on tensor cores: out = A2 @ B2^T + bd
    decode_mma_kernel<<<dim3(40, 256), 256>>>(A2, B2, bd, out);
}